// round 13
// baseline (speedup 1.0000x reference)
#include <cuda_runtime.h>
#include <cstdint>
#include <math.h>

#define NMAX 50000
#define EMAX 800000
#define DIM 128

// ---------------- scratch (device globals; no allocation allowed) ----------------
__device__ float g_h[(size_t)NMAX * DIM];
__device__ float g_t[(size_t)NMAX * DIM];
__device__ float g_embW[44 * DIM];           // emb @ lin_W[:, :128]^T
__device__ int   g_idx[NMAX];
__device__ float g_dinv[NMAX];
__device__ int   g_cnt[NMAX];                // INVARIANT: zero at entry (zero-init + re-zeroed by scan3)
__device__ int   g_rowstart[NMAX + 1];
__device__ int   g_cursor[NMAX];
__device__ int   g_col[EMAX];
__device__ int   g_part[256];
__device__ int   g_is64;

// packed fp32x2 FMA (sm_103): d = a*b + d on 2 packed floats
#define FMA2(d, a, b) \
    asm("fma.rn.f32x2 %0, %1, %2, %0;" : "+l"(d) : "l"(a), "l"(b))
#define UNPACK2(lo, hi, v) \
    asm("mov.b64 {%0, %1}, %2;" : "=r"(lo), "=r"(hi) : "l"(v))

__device__ __forceinline__ int load_edge(const void* edge, size_t pos, int is64) {
    if (is64) return (int)((const long long*)edge)[pos];
    return ((const int*)edge)[pos];
}

// ================= L1: prep(argmax) + count + embW, role-partitioned =================
__global__ void misc1_kernel(const float* __restrict__ x, const void* __restrict__ edge,
                             const float* __restrict__ emb, const float* __restrict__ linW,
                             int n, int e, int PB, int CB)
{
    const int b = blockIdx.x, tid = threadIdx.x;
    if (b < PB) {
        // ---- prep role: warp per node ----
        int gw = b * 8 + (tid >> 5), lane = tid & 31;
        if (gw >= n) return;
        const float* xi = x + (size_t)gw * 78;
        float best = -1e38f; int bi = 1 << 30;
        for (int k = lane; k < 44; k += 32) {
            float v = xi[k];
            if (v > best || (v == best && k < bi)) { best = v; bi = k; }
        }
        for (int off = 16; off; off >>= 1) {
            float ov = __shfl_xor_sync(0xffffffffu, best, off);
            int   oi = __shfl_xor_sync(0xffffffffu, bi, off);
            if (ov > best || (ov == best && oi < bi)) { best = ov; bi = oi; }
        }
        if (lane == 0) g_idx[gw] = bi;
    } else if (b < PB + CB) {
        // ---- count role (per-block edge dtype detect; g_cnt zero at entry) ----
        int w = (tid < 128) ? ((const int*)edge)[2 * tid + 1] : 0;
        int any = __syncthreads_or(w);
        int is64 = (any == 0) ? 1 : 0;
        if (tid == 0 && b == PB) g_is64 = is64;
        int i = (b - PB) * 256 + tid;
        if (i < e) {
            int d = load_edge(edge, (size_t)e + i, is64);
            atomicAdd(&g_cnt[d], 1);
        }
    } else {
        // ---- embW role: 2 rows per block ----
        int r = (b - PB - CB) * 2 + (tid >> 7), o = tid & 127;
        if (r < 44) {
            const float* er = emb + r * 128;
            const float* wr = linW + (size_t)o * 162;
            float acc = 0.f;
            #pragma unroll 8
            for (int k = 0; k < 128; k++) acc = fmaf(er[k], wr[k], acc);
            g_embW[r * 128 + o] = acc;
        }
    }
}

// ================= L2: per-block reduce of counts =================
__global__ void scan1_kernel(int n) {
    __shared__ int wsum[8];
    int i = blockIdx.x * 256 + threadIdx.x;
    int lane = threadIdx.x & 31, wid = threadIdx.x >> 5;
    int v = (i < n) ? g_cnt[i] : 0;
    for (int off = 16; off; off >>= 1) v += __shfl_xor_sync(0xffffffffu, v, off);
    if (lane == 0) wsum[wid] = v;
    __syncthreads();
    if (threadIdx.x == 0) {
        int s = 0;
        #pragma unroll
        for (int w = 0; w < 8; w++) s += wsum[w];
        g_part[blockIdx.x] = s;
    }
}

// ================= L3: block scan + cross-block offset from parts; re-zeroes cnt =================
__global__ void scan3_kernel(int n, int nb) {
    __shared__ int redsh[8];
    __shared__ int scansh[8];
    __shared__ int off_sh;
    const int tid = threadIdx.x, lane = tid & 31, wid = tid >> 5, b = blockIdx.x;

    int p = (tid < b) ? g_part[tid] : 0;
    for (int off = 16; off; off >>= 1) p += __shfl_xor_sync(0xffffffffu, p, off);
    if (lane == 0) redsh[wid] = p;
    __syncthreads();
    if (tid == 0) {
        int s = 0;
        #pragma unroll
        for (int w = 0; w < 8; w++) s += redsh[w];
        off_sh = s;
    }
    __syncthreads();
    const int offset = off_sh;

    int i = b * 256 + tid;
    int v = (i < n) ? g_cnt[i] : 0;
    int xx = v;
    #pragma unroll
    for (int off = 1; off < 32; off <<= 1) {
        int t = __shfl_up_sync(0xffffffffu, xx, off);
        if (lane >= off) xx += t;
    }
    if (lane == 31) scansh[wid] = xx;
    __syncthreads();
    if (wid == 0 && lane < 8) {
        int y = scansh[lane];
        #pragma unroll
        for (int off = 1; off < 8; off <<= 1) {
            int t = __shfl_up_sync(0xffu, y, off);
            if (lane >= off) y += t;
        }
        scansh[lane] = y;
    }
    __syncthreads();
    if (i < n) {
        int start = offset + xx + (wid ? scansh[wid - 1] : 0) - v;
        g_rowstart[i] = start;
        g_cursor[i]   = start;
        g_dinv[i]     = rsqrtf((float)(v + 1));   // +1 self loop
        g_cnt[i]      = 0;                        // restore invariant
    }
    if (b == nb - 1 && tid == 0) g_rowstart[n] = offset + scansh[7];
}

// ================= L4: fill + front fused as block roles (1024 threads) =================
// blocks [0, FB): front role (32 nodes each, W-in-registers);
// blocks [FB, FB+FCB): fill role (1024 edges each)
__global__ void __launch_bounds__(1024) fillFront_kernel(
    const float* __restrict__ x, const float* __restrict__ linW,
    const float* __restrict__ linb, const void* __restrict__ edge,
    int n, int e, int FB)
{
    const int b = blockIdx.x, tid = threadIdx.x;
    if (b >= FB) {
        // ---- fill role ----
        int i = (b - FB) * 1024 + tid;
        if (i < e) {
            int is64 = g_is64;
            int s = load_edge(edge, (size_t)i, is64);
            int d = load_edge(edge, (size_t)e + i, is64);
            int p = atomicAdd(&g_cursor[d], 1);
            g_col[p] = s;
        }
        return;
    }
    // ---- front role: h = relu(embW[idx] + xfix @ Wfix^T + b) ----
    // thread owns output o = tid&127; group g = tid>>7 (8 groups) handles 4 nodes each.
    __shared__ float Wf[128 * 34];   // Wfix[o][k] = lin_W[o][128+k], pitch 34
    __shared__ float sxf[32 * 34];   // xfix per node
    const int base = b * 32;

    for (int idx = tid; idx < 128 * 34; idx += 1024) {
        int o = idx / 34, k = idx - o * 34;
        Wf[idx] = linW[(size_t)o * 162 + 128 + k];
    }
    for (int idx = tid; idx < 32 * 34; idx += 1024) {
        int nd = idx / 34, k = idx - nd * 34;
        int gi = base + nd;
        sxf[idx] = (gi < n) ? x[(size_t)gi * 78 + 44 + k] : 0.f;
    }
    __syncthreads();

    const int o = tid & 127, g = tid >> 7;
    // hoist W row into registers (one-time smem read)
    unsigned long long wreg[17];
    const unsigned long long* wp = (const unsigned long long*)(Wf + o * 34);
    #pragma unroll
    for (int i = 0; i < 17; i++) wreg[i] = wp[i];
    const float bo = linb[o];

    #pragma unroll
    for (int r = 0; r < 4; r++) {
        int nd = g * 4 + r;
        int gi = base + nd;
        if (gi >= n) continue;
        unsigned long long a0 = 0ull, a1 = 0ull;
        const unsigned long long* xp = (const unsigned long long*)(sxf + nd * 34);
        #pragma unroll
        for (int i = 0; i < 16; i += 2) {
            FMA2(a0, wreg[i],     xp[i]);       // xp: broadcast (conflict-free)
            FMA2(a1, wreg[i + 1], xp[i + 1]);
        }
        FMA2(a0, wreg[16], xp[16]);
        unsigned l0, h0, l1, h1;
        UNPACK2(l0, h0, a0); UNPACK2(l1, h1, a1);
        float s = __uint_as_float(l0) + __uint_as_float(h0)
                + __uint_as_float(l1) + __uint_as_float(h1);
        float er = g_embW[g_idx[gi] * 128 + o];    // coalesced row read
        g_h[(size_t)gi * 128 + o] = fmaxf(s + er + bo, 0.f);   // coalesced write
    }
}

// ================= square GEMM out[n,128] = A[n,128] @ W[128,128]^T (f32x2 K-packed) =================
__global__ void __launch_bounds__(256) gemm2_kernel(
    const float* __restrict__ A, const float* __restrict__ W,
    float* __restrict__ out, int n)
{
    extern __shared__ float sm[];
    float* Ws = sm;              // 128 x 128
    float* Fs = sm + 128 * 128;  // 64 x 128
    const int tid  = threadIdx.x;
    const int base = blockIdx.x * 64;

    #pragma unroll
    for (int i = 0; i < 16; i++) {
        int idx = tid + i * 256;
        int o = idx >> 5, q = idx & 31;
        float4 v = *(const float4*)(W + (size_t)o * 128 + q * 4);
        *(float4*)(Ws + o * 128 + ((q ^ (o & 15)) * 4)) = v;
    }
    #pragma unroll
    for (int i = 0; i < 8; i++) {
        int idx = tid + i * 256;
        int nd = idx >> 5, q = idx & 31;
        int gi = base + nd;
        float4 v = (gi < n) ? *(const float4*)(A + (size_t)gi * 128 + q * 4)
                            : make_float4(0.f, 0.f, 0.f, 0.f);
        *(float4*)(Fs + nd * 128 + ((q ^ (nd & 15)) * 4)) = v;
    }
    __syncthreads();

    const int tx = tid & 15, ty = tid >> 4;
    unsigned long long acc[8][4];
    #pragma unroll
    for (int j = 0; j < 8; j++)
        #pragma unroll
        for (int m = 0; m < 4; m++) acc[j][m] = 0ull;

    #pragma unroll 8
    for (int kq = 0; kq < 32; kq++) {
        ulonglong2 wv[8];
        #pragma unroll
        for (int j = 0; j < 8; j++)
            wv[j] = *(const ulonglong2*)(Ws + (tx + 16 * j) * 128 + ((kq ^ tx) * 4));
        ulonglong2 fv[4];
        #pragma unroll
        for (int m = 0; m < 4; m++) {
            int nd = ty * 4 + m;
            fv[m] = *(const ulonglong2*)(Fs + nd * 128 + ((kq ^ (nd & 15)) * 4));
        }
        #pragma unroll
        for (int j = 0; j < 8; j++)
            #pragma unroll
            for (int m = 0; m < 4; m++) {
                FMA2(acc[j][m], wv[j].x, fv[m].x);
                FMA2(acc[j][m], wv[j].y, fv[m].y);
            }
    }

    #pragma unroll
    for (int m = 0; m < 4; m++) {
        int gi = base + ty * 4 + m;
        if (gi < n) {
            #pragma unroll
            for (int j = 0; j < 8; j++) {
                unsigned lo, hi; UNPACK2(lo, hi, acc[j][m]);
                out[(size_t)gi * 128 + tx + 16 * j] = __uint_as_float(lo) + __uint_as_float(hi);
            }
        }
    }
}

// ================= CSR gather aggregation, 4-edge unrolled =================
__global__ void agg_kernel(const float* __restrict__ t, const float* __restrict__ bias,
                           float* __restrict__ out, int n)
{
    int gw   = (blockIdx.x * blockDim.x + threadIdx.x) >> 5;
    int lane = threadIdx.x & 31;
    if (gw >= n) return;
    int r0 = g_rowstart[gw], r1 = g_rowstart[gw + 1];
    const float4* t4 = (const float4*)t;

    float4 a0 = make_float4(0.f, 0.f, 0.f, 0.f);
    float4 a1 = make_float4(0.f, 0.f, 0.f, 0.f);
    int e = r0;
    for (; e + 3 < r1; e += 4) {
        int s0 = g_col[e],     s1 = g_col[e + 1];
        int s2 = g_col[e + 2], s3 = g_col[e + 3];
        float w0 = g_dinv[s0], w1 = g_dinv[s1], w2 = g_dinv[s2], w3 = g_dinv[s3];
        float4 v0 = t4[(size_t)s0 * 32 + lane];
        float4 v1 = t4[(size_t)s1 * 32 + lane];
        float4 v2 = t4[(size_t)s2 * 32 + lane];
        float4 v3 = t4[(size_t)s3 * 32 + lane];
        a0.x = fmaf(w0, v0.x, a0.x); a0.y = fmaf(w0, v0.y, a0.y);
        a0.z = fmaf(w0, v0.z, a0.z); a0.w = fmaf(w0, v0.w, a0.w);
        a1.x = fmaf(w1, v1.x, a1.x); a1.y = fmaf(w1, v1.y, a1.y);
        a1.z = fmaf(w1, v1.z, a1.z); a1.w = fmaf(w1, v1.w, a1.w);
        a0.x = fmaf(w2, v2.x, a0.x); a0.y = fmaf(w2, v2.y, a0.y);
        a0.z = fmaf(w2, v2.z, a0.z); a0.w = fmaf(w2, v2.w, a0.w);
        a1.x = fmaf(w3, v3.x, a1.x); a1.y = fmaf(w3, v3.y, a1.y);
        a1.z = fmaf(w3, v3.z, a1.z); a1.w = fmaf(w3, v3.w, a1.w);
    }
    for (; e < r1; e++) {
        int s = g_col[e];
        float w = g_dinv[s];
        float4 v = t4[(size_t)s * 32 + lane];
        a0.x = fmaf(w, v.x, a0.x); a0.y = fmaf(w, v.y, a0.y);
        a0.z = fmaf(w, v.z, a0.z); a0.w = fmaf(w, v.w, a0.w);
    }
    float di  = g_dinv[gw];
    float di2 = di * di;
    float4 sv = t4[(size_t)gw * 32 + lane];
    float4 b4 = ((const float4*)bias)[lane];
    float4 o;
    o.x = fmaxf(di * (a0.x + a1.x) + di2 * sv.x + b4.x, 0.f);
    o.y = fmaxf(di * (a0.y + a1.y) + di2 * sv.y + b4.y, 0.f);
    o.z = fmaxf(di * (a0.z + a1.z) + di2 * sv.z + b4.z, 0.f);
    o.w = fmaxf(di * (a0.w + a1.w) + di2 * sv.w + b4.w, 0.f);
    ((float4*)out)[(size_t)gw * 32 + lane] = o;
}

// ---------------- launch: serial single stream (graph-friendly) ----------------
extern "C" void kernel_launch(void* const* d_in, const int* in_sizes, int n_in,
                              void* d_out, int out_size)
{
    const float* x     = (const float*)d_in[0];
    const void*  edge  = d_in[1];
    const float* emb   = (const float*)d_in[3];
    const float* lin_W = (const float*)d_in[4];
    const float* lin_b = (const float*)d_in[5];
    const float* g1W   = (const float*)d_in[6];
    const float* g1b   = (const float*)d_in[7];
    const float* g2W   = (const float*)d_in[8];
    const float* g2b   = (const float*)d_in[9];

    int n = in_sizes[0] / 78;
    int e = in_sizes[1] / 2;
    float* out = (float*)d_out;

    float *h_, *t_;
    cudaGetSymbolAddress((void**)&h_, g_h);
    cudaGetSymbolAddress((void**)&t_, g_t);

    const int GSMEM = (128 * 128 + 64 * 128) * 4;   // 98304
    cudaFuncSetAttribute(gemm2_kernel, cudaFuncAttributeMaxDynamicSharedMemorySize, GSMEM);

    int PB  = (n + 7) / 8;          // prep blocks
    int CB  = (e + 255) / 256;      // count blocks (256 thr)
    int WB  = 22;                   // embW blocks (2 rows each)
    int nb  = (n + 255) / 256;      // scan blocks (<=256)
    int FB  = (n + 31) / 32;        // front blocks (1024 thr)
    int FCB = (e + 1023) / 1024;    // fill blocks (1024 thr)
    int ggrid = (n + 63) / 64;
    int ngrid_warp = (n + 7) / 8;

    misc1_kernel<<<PB + CB + WB, 256>>>(x, edge, emb, lin_W, n, e, PB, CB);
    scan1_kernel<<<nb, 256>>>(n);
    scan3_kernel<<<nb, 256>>>(n, nb);
    fillFront_kernel<<<FB + FCB, 1024>>>(x, lin_W, lin_b, edge, n, e, FB);
    // layer 1
    gemm2_kernel<<<ggrid, 256, GSMEM>>>(h_, g1W, t_, n);
    agg_kernel<<<ngrid_warp, 256>>>(t_, g1b, h_, n);
    // layer 2
    gemm2_kernel<<<ggrid, 256, GSMEM>>>(h_, g2W, t_, n);
    agg_kernel<<<ngrid_warp, 256>>>(t_, g2b, out, n);
}

// round 14
// speedup vs baseline: 1.0423x; 1.0423x over previous
#include <cuda_runtime.h>
#include <cstdint>
#include <math.h>

#define NMAX 50000
#define EMAX 800000
#define DIM 128

// ---------------- scratch (device globals; no allocation allowed) ----------------
__device__ float g_h[(size_t)NMAX * DIM];
__device__ float g_t[(size_t)NMAX * DIM];
__device__ float g_embW[44 * DIM];           // emb @ lin_W[:, :128]^T
__device__ int   g_idx[NMAX];
__device__ float g_dinv[NMAX];
__device__ int   g_cnt[NMAX];                // INVARIANT: zero at entry (zero-init + re-zeroed by scan3)
__device__ int   g_rowstart[NMAX + 1];
__device__ int   g_cursor[NMAX];
__device__ int   g_col[EMAX];
__device__ int   g_part[256];
__device__ int   g_is64;

// packed fp32x2 FMA (sm_103): d = a*b + d on 2 packed floats
#define FMA2(d, a, b) \
    asm("fma.rn.f32x2 %0, %1, %2, %0;" : "+l"(d) : "l"(a), "l"(b))
#define UNPACK2(lo, hi, v) \
    asm("mov.b64 {%0, %1}, %2;" : "=r"(lo), "=r"(hi) : "l"(v))

__device__ __forceinline__ int load_edge(const void* edge, size_t pos, int is64) {
    if (is64) return (int)((const long long*)edge)[pos];
    return ((const int*)edge)[pos];
}

// ================= L1: prep(argmax) + count + embW, role-partitioned =================
__global__ void misc1_kernel(const float* __restrict__ x, const void* __restrict__ edge,
                             const float* __restrict__ emb, const float* __restrict__ linW,
                             int n, int e, int PB, int CB)
{
    const int b = blockIdx.x, tid = threadIdx.x;
    if (b < PB) {
        // ---- prep role: warp per node ----
        int gw = b * 8 + (tid >> 5), lane = tid & 31;
        if (gw >= n) return;
        const float* xi = x + (size_t)gw * 78;
        float best = -1e38f; int bi = 1 << 30;
        for (int k = lane; k < 44; k += 32) {
            float v = xi[k];
            if (v > best || (v == best && k < bi)) { best = v; bi = k; }
        }
        for (int off = 16; off; off >>= 1) {
            float ov = __shfl_xor_sync(0xffffffffu, best, off);
            int   oi = __shfl_xor_sync(0xffffffffu, bi, off);
            if (ov > best || (ov == best && oi < bi)) { best = ov; bi = oi; }
        }
        if (lane == 0) g_idx[gw] = bi;
    } else if (b < PB + CB) {
        // ---- count role (per-block edge dtype detect; g_cnt zero at entry) ----
        int w = (tid < 128) ? ((const int*)edge)[2 * tid + 1] : 0;
        int any = __syncthreads_or(w);
        int is64 = (any == 0) ? 1 : 0;
        if (tid == 0 && b == PB) g_is64 = is64;
        int i = (b - PB) * 256 + tid;
        if (i < e) {
            int d = load_edge(edge, (size_t)e + i, is64);
            atomicAdd(&g_cnt[d], 1);
        }
    } else {
        // ---- embW role: 2 rows per block ----
        int r = (b - PB - CB) * 2 + (tid >> 7), o = tid & 127;
        if (r < 44) {
            const float* er = emb + r * 128;
            const float* wr = linW + (size_t)o * 162;
            float acc = 0.f;
            #pragma unroll 8
            for (int k = 0; k < 128; k++) acc = fmaf(er[k], wr[k], acc);
            g_embW[r * 128 + o] = acc;
        }
    }
}

// ================= L2: per-block reduce of counts =================
__global__ void scan1_kernel(int n) {
    __shared__ int wsum[8];
    int i = blockIdx.x * 256 + threadIdx.x;
    int lane = threadIdx.x & 31, wid = threadIdx.x >> 5;
    int v = (i < n) ? g_cnt[i] : 0;
    for (int off = 16; off; off >>= 1) v += __shfl_xor_sync(0xffffffffu, v, off);
    if (lane == 0) wsum[wid] = v;
    __syncthreads();
    if (threadIdx.x == 0) {
        int s = 0;
        #pragma unroll
        for (int w = 0; w < 8; w++) s += wsum[w];
        g_part[blockIdx.x] = s;
    }
}

// ================= L3: block scan + cross-block offset from parts; re-zeroes cnt =================
__global__ void scan3_kernel(int n, int nb) {
    __shared__ int redsh[8];
    __shared__ int scansh[8];
    __shared__ int off_sh;
    const int tid = threadIdx.x, lane = tid & 31, wid = tid >> 5, b = blockIdx.x;

    int p = (tid < b) ? g_part[tid] : 0;
    for (int off = 16; off; off >>= 1) p += __shfl_xor_sync(0xffffffffu, p, off);
    if (lane == 0) redsh[wid] = p;
    __syncthreads();
    if (tid == 0) {
        int s = 0;
        #pragma unroll
        for (int w = 0; w < 8; w++) s += redsh[w];
        off_sh = s;
    }
    __syncthreads();
    const int offset = off_sh;

    int i = b * 256 + tid;
    int v = (i < n) ? g_cnt[i] : 0;
    int xx = v;
    #pragma unroll
    for (int off = 1; off < 32; off <<= 1) {
        int t = __shfl_up_sync(0xffffffffu, xx, off);
        if (lane >= off) xx += t;
    }
    if (lane == 31) scansh[wid] = xx;
    __syncthreads();
    if (wid == 0 && lane < 8) {
        int y = scansh[lane];
        #pragma unroll
        for (int off = 1; off < 8; off <<= 1) {
            int t = __shfl_up_sync(0xffu, y, off);
            if (lane >= off) y += t;
        }
        scansh[lane] = y;
    }
    __syncthreads();
    if (i < n) {
        int start = offset + xx + (wid ? scansh[wid - 1] : 0) - v;
        g_rowstart[i] = start;
        g_cursor[i]   = start;
        g_dinv[i]     = rsqrtf((float)(v + 1));   // +1 self loop
        g_cnt[i]      = 0;                        // restore invariant
    }
    if (b == nb - 1 && tid == 0) g_rowstart[n] = offset + scansh[7];
}

// ================= L4: fill CSR (own kernel, high occupancy) =================
__global__ void fill_kernel(const void* __restrict__ edge, int e) {
    int i = blockIdx.x * blockDim.x + threadIdx.x;
    if (i >= e) return;
    int is64 = g_is64;
    int s = load_edge(edge, (size_t)i, is64);
    int d = load_edge(edge, (size_t)e + i, is64);
    int p = atomicAdd(&g_cursor[d], 1);
    g_col[p] = s;
}

// ================= L5: front v3: h = relu(embW[idx] + xfix @ Wfix^T + b) =================
// 256 threads = 8 warps; warp handles 4 nodes; lane owns outs l+32q (q=0..3).
// Wp staged k-major as u64 pairs -> conflict-free lane-consecutive LDS.64;
// x reads broadcast; each W read feeds 4 nodes (amortized).
__global__ void __launch_bounds__(256) front_kernel(
    const float* __restrict__ x, const float* __restrict__ linW,
    const float* __restrict__ linb, int n)
{
    __shared__ unsigned long long Wp[17 * 128];  // [kp][o] = (W[o][128+2kp], W[o][128+2kp+1])
    __shared__ float xs[32 * 34];                // xfix per node, pitch 34
    const int tid  = threadIdx.x;
    const int base = blockIdx.x * 32;

    for (int idx = tid; idx < 17 * 128; idx += 256) {
        int kp = idx >> 7, o = idx & 127;
        float2 v = *(const float2*)(linW + (size_t)o * 162 + 128 + 2 * kp);
        Wp[kp * 128 + o] = *(const unsigned long long*)&v;
    }
    for (int idx = tid; idx < 32 * 34; idx += 256) {
        int nd = idx / 34, k = idx - nd * 34;
        int gi = base + nd;
        xs[idx] = (gi < n) ? x[(size_t)gi * 78 + 44 + k] : 0.f;
    }
    __syncthreads();

    const int w = tid >> 5, l = tid & 31;   // warp w: nodes base+4w..base+4w+3
    unsigned long long acc[4][4];           // [q][m]
    #pragma unroll
    for (int q = 0; q < 4; q++)
        #pragma unroll
        for (int m = 0; m < 4; m++) acc[q][m] = 0ull;

    #pragma unroll
    for (int kp = 0; kp < 17; kp++) {
        unsigned long long wq[4];
        #pragma unroll
        for (int q = 0; q < 4; q++) wq[q] = Wp[kp * 128 + l + 32 * q];
        unsigned long long xm[4];
        #pragma unroll
        for (int m = 0; m < 4; m++)
            xm[m] = *(const unsigned long long*)(xs + (w * 4 + m) * 34 + 2 * kp);  // broadcast
        #pragma unroll
        for (int q = 0; q < 4; q++)
            #pragma unroll
            for (int m = 0; m < 4; m++)
                FMA2(acc[q][m], wq[q], xm[m]);
    }

    #pragma unroll
    for (int m = 0; m < 4; m++) {
        int gi = base + w * 4 + m;
        if (gi >= n) continue;
        const float* er = g_embW + g_idx[gi] * 128;
        #pragma unroll
        for (int q = 0; q < 4; q++) {
            int o = l + 32 * q;
            unsigned lo, hi; UNPACK2(lo, hi, acc[q][m]);
            float v = __uint_as_float(lo) + __uint_as_float(hi) + er[o] + linb[o];
            g_h[(size_t)gi * 128 + o] = fmaxf(v, 0.f);   // coalesced
        }
    }
}

// ================= square GEMM out[n,128] = A[n,128] @ W[128,128]^T (f32x2 K-packed) =================
__global__ void __launch_bounds__(256) gemm2_kernel(
    const float* __restrict__ A, const float* __restrict__ W,
    float* __restrict__ out, int n)
{
    extern __shared__ float sm[];
    float* Ws = sm;              // 128 x 128
    float* Fs = sm + 128 * 128;  // 64 x 128
    const int tid  = threadIdx.x;
    const int base = blockIdx.x * 64;

    #pragma unroll
    for (int i = 0; i < 16; i++) {
        int idx = tid + i * 256;
        int o = idx >> 5, q = idx & 31;
        float4 v = *(const float4*)(W + (size_t)o * 128 + q * 4);
        *(float4*)(Ws + o * 128 + ((q ^ (o & 15)) * 4)) = v;
    }
    #pragma unroll
    for (int i = 0; i < 8; i++) {
        int idx = tid + i * 256;
        int nd = idx >> 5, q = idx & 31;
        int gi = base + nd;
        float4 v = (gi < n) ? *(const float4*)(A + (size_t)gi * 128 + q * 4)
                            : make_float4(0.f, 0.f, 0.f, 0.f);
        *(float4*)(Fs + nd * 128 + ((q ^ (nd & 15)) * 4)) = v;
    }
    __syncthreads();

    const int tx = tid & 15, ty = tid >> 4;
    unsigned long long acc[8][4];
    #pragma unroll
    for (int j = 0; j < 8; j++)
        #pragma unroll
        for (int m = 0; m < 4; m++) acc[j][m] = 0ull;

    #pragma unroll 8
    for (int kq = 0; kq < 32; kq++) {
        ulonglong2 wv[8];
        #pragma unroll
        for (int j = 0; j < 8; j++)
            wv[j] = *(const ulonglong2*)(Ws + (tx + 16 * j) * 128 + ((kq ^ tx) * 4));
        ulonglong2 fv[4];
        #pragma unroll
        for (int m = 0; m < 4; m++) {
            int nd = ty * 4 + m;
            fv[m] = *(const ulonglong2*)(Fs + nd * 128 + ((kq ^ (nd & 15)) * 4));
        }
        #pragma unroll
        for (int j = 0; j < 8; j++)
            #pragma unroll
            for (int m = 0; m < 4; m++) {
                FMA2(acc[j][m], wv[j].x, fv[m].x);
                FMA2(acc[j][m], wv[j].y, fv[m].y);
            }
    }

    #pragma unroll
    for (int m = 0; m < 4; m++) {
        int gi = base + ty * 4 + m;
        if (gi < n) {
            #pragma unroll
            for (int j = 0; j < 8; j++) {
                unsigned lo, hi; UNPACK2(lo, hi, acc[j][m]);
                out[(size_t)gi * 128 + tx + 16 * j] = __uint_as_float(lo) + __uint_as_float(hi);
            }
        }
    }
}

// ================= CSR gather aggregation, 4-edge unrolled =================
__global__ void agg_kernel(const float* __restrict__ t, const float* __restrict__ bias,
                           float* __restrict__ out, int n)
{
    int gw   = (blockIdx.x * blockDim.x + threadIdx.x) >> 5;
    int lane = threadIdx.x & 31;
    if (gw >= n) return;
    int r0 = g_rowstart[gw], r1 = g_rowstart[gw + 1];
    const float4* t4 = (const float4*)t;

    float4 a0 = make_float4(0.f, 0.f, 0.f, 0.f);
    float4 a1 = make_float4(0.f, 0.f, 0.f, 0.f);
    int e = r0;
    for (; e + 3 < r1; e += 4) {
        int s0 = g_col[e],     s1 = g_col[e + 1];
        int s2 = g_col[e + 2], s3 = g_col[e + 3];
        float w0 = g_dinv[s0], w1 = g_dinv[s1], w2 = g_dinv[s2], w3 = g_dinv[s3];
        float4 v0 = t4[(size_t)s0 * 32 + lane];
        float4 v1 = t4[(size_t)s1 * 32 + lane];
        float4 v2 = t4[(size_t)s2 * 32 + lane];
        float4 v3 = t4[(size_t)s3 * 32 + lane];
        a0.x = fmaf(w0, v0.x, a0.x); a0.y = fmaf(w0, v0.y, a0.y);
        a0.z = fmaf(w0, v0.z, a0.z); a0.w = fmaf(w0, v0.w, a0.w);
        a1.x = fmaf(w1, v1.x, a1.x); a1.y = fmaf(w1, v1.y, a1.y);
        a1.z = fmaf(w1, v1.z, a1.z); a1.w = fmaf(w1, v1.w, a1.w);
        a0.x = fmaf(w2, v2.x, a0.x); a0.y = fmaf(w2, v2.y, a0.y);
        a0.z = fmaf(w2, v2.z, a0.z); a0.w = fmaf(w2, v2.w, a0.w);
        a1.x = fmaf(w3, v3.x, a1.x); a1.y = fmaf(w3, v3.y, a1.y);
        a1.z = fmaf(w3, v3.z, a1.z); a1.w = fmaf(w3, v3.w, a1.w);
    }
    for (; e < r1; e++) {
        int s = g_col[e];
        float w = g_dinv[s];
        float4 v = t4[(size_t)s * 32 + lane];
        a0.x = fmaf(w, v.x, a0.x); a0.y = fmaf(w, v.y, a0.y);
        a0.z = fmaf(w, v.z, a0.z); a0.w = fmaf(w, v.w, a0.w);
    }
    float di  = g_dinv[gw];
    float di2 = di * di;
    float4 sv = t4[(size_t)gw * 32 + lane];
    float4 b4 = ((const float4*)bias)[lane];
    float4 o;
    o.x = fmaxf(di * (a0.x + a1.x) + di2 * sv.x + b4.x, 0.f);
    o.y = fmaxf(di * (a0.y + a1.y) + di2 * sv.y + b4.y, 0.f);
    o.z = fmaxf(di * (a0.z + a1.z) + di2 * sv.z + b4.z, 0.f);
    o.w = fmaxf(di * (a0.w + a1.w) + di2 * sv.w + b4.w, 0.f);
    ((float4*)out)[(size_t)gw * 32 + lane] = o;
}

// ---------------- launch: serial single stream (graph-friendly) ----------------
extern "C" void kernel_launch(void* const* d_in, const int* in_sizes, int n_in,
                              void* d_out, int out_size)
{
    const float* x     = (const float*)d_in[0];
    const void*  edge  = d_in[1];
    const float* emb   = (const float*)d_in[3];
    const float* lin_W = (const float*)d_in[4];
    const float* lin_b = (const float*)d_in[5];
    const float* g1W   = (const float*)d_in[6];
    const float* g1b   = (const float*)d_in[7];
    const float* g2W   = (const float*)d_in[8];
    const float* g2b   = (const float*)d_in[9];

    int n = in_sizes[0] / 78;
    int e = in_sizes[1] / 2;
    float* out = (float*)d_out;

    float *h_, *t_;
    cudaGetSymbolAddress((void**)&h_, g_h);
    cudaGetSymbolAddress((void**)&t_, g_t);

    const int GSMEM = (128 * 128 + 64 * 128) * 4;   // 98304
    cudaFuncSetAttribute(gemm2_kernel, cudaFuncAttributeMaxDynamicSharedMemorySize, GSMEM);

    int PB  = (n + 7) / 8;          // prep blocks
    int CB  = (e + 255) / 256;      // count/fill blocks (256 thr)
    int WB  = 22;                   // embW blocks (2 rows each)
    int nb  = (n + 255) / 256;      // scan blocks (<=256)
    int FB  = (n + 31) / 32;        // front blocks (256 thr, 32 nodes each)
    int ggrid = (n + 63) / 64;
    int ngrid_warp = (n + 7) / 8;

    misc1_kernel<<<PB + CB + WB, 256>>>(x, edge, emb, lin_W, n, e, PB, CB);
    scan1_kernel<<<nb, 256>>>(n);
    scan3_kernel<<<nb, 256>>>(n, nb);
    fill_kernel<<<CB, 256>>>(edge, e);
    front_kernel<<<FB, 256>>>(x, lin_W, lin_b, n);
    // layer 1
    gemm2_kernel<<<ggrid, 256, GSMEM>>>(h_, g1W, t_, n);
    agg_kernel<<<ngrid_warp, 256>>>(t_, g1b, h_, n);
    // layer 2
    gemm2_kernel<<<ggrid, 256, GSMEM>>>(h_, g2W, t_, n);
    agg_kernel<<<ngrid_warp, 256>>>(t_, g2b, out, n);
}